// round 2
// baseline (speedup 1.0000x reference)
#include <cuda_runtime.h>
#include <cuda_bf16.h>

// Problem constants (fixed by the dataset)
constexpr int N_NODES  = 131072;
constexpr int N_EDGES  = 2097152;
constexpr int N_GRAPHS = 2048;
constexpr int HID      = 64;
constexpr int IN_CH    = 12;
constexpr int OUT_CH   = 4;

// ---------------- scratch (device globals; no allocation allowed) ----------
__device__ float g_hs [N_NODES * HID];   // h * dinv (layer input scaled), reused in place
__device__ float g_agg[N_NODES * HID];   // scatter accumulator, reused between layers
__device__ float g_deg[N_NODES];         // degree -> dinv (in place)
__device__ float g_gsum[N_GRAPHS * HID]; // pooled sums
__device__ float g_gcnt[N_GRAPHS];       // pooled counts
__device__ int   g_is64;                 // 1 if index tensors are int64, 0 if int32

// ---------------- helpers --------------------------------------------------
__device__ __forceinline__ void red_add_v4(float* p, float4 v) {
    asm volatile("red.global.add.v4.f32 [%0], {%1,%2,%3,%4};"
                 :: "l"(p), "f"(v.x), "f"(v.y), "f"(v.z), "f"(v.w) : "memory");
}
__device__ __forceinline__ void red_add_f32(float* p, float v) {
    asm volatile("red.global.add.f32 [%0], %1;" :: "l"(p), "f"(v) : "memory");
}
// Load index i from a tensor that is either int32 or int64 (flag-selected).
__device__ __forceinline__ int load_idx(const void* p, long i, int is64) {
    return is64 ? (int)((const long long*)p)[i] : ((const int*)p)[i];
}

// ---------------- kernels --------------------------------------------------

// Detect index dtype: sample odd 32-bit words of edge_index. int64 values
// < 2^32 have zero high words; int32 data has random nonzero words there.
__global__ void k_detect(const void* __restrict__ ei) {
    if (threadIdx.x != 0 || blockIdx.x != 0) return;
    const int* p = (const int*)ei;
    int nz = 0;
    #pragma unroll 8
    for (int i = 0; i < 512; ++i) nz += (p[2 * i + 1] != 0);
    g_is64 = (nz == 0) ? 1 : 0;
}

// Zero all accumulators (agg, deg, gsum, gcnt).
__global__ void k_zero() {
    long i = (long)blockIdx.x * blockDim.x + threadIdx.x;
    if (i < (long)N_NODES * HID) g_agg[i] = 0.0f;
    if (i < N_NODES)             g_deg[i] = 0.0f;
    if (i < N_GRAPHS * HID)      g_gsum[i] = 0.0f;
    if (i < N_GRAPHS)            g_gcnt[i] = 0.0f;
}

// In-degree at dst (self-loop +1 handled in k_dinv).
__global__ void k_deg(const void* __restrict__ ei) {
    int e = blockIdx.x * blockDim.x + threadIdx.x;
    if (e >= N_EDGES) return;
    int is64 = g_is64;
    int d = load_idx(ei, (long)N_EDGES + e, is64);
    red_add_f32(&g_deg[d], 1.0f);
}

// deg -> dinv = rsqrt(deg + 1), in place.
__global__ void k_dinv() {
    int i = blockIdx.x * blockDim.x + threadIdx.x;
    if (i < N_NODES) g_deg[i] = rsqrtf(g_deg[i] + 1.0f);
}

// hs = (x @ W1) * dinv.  256 threads = 4 nodes x 64 ch; 8 node-groups per block.
__global__ void k_xw1(const float* __restrict__ x, const float* __restrict__ W1) {
    __shared__ float W1s[IN_CH * HID];
    __shared__ float xs[4][IN_CH];
    int t = threadIdx.x;
    for (int i = t; i < IN_CH * HID; i += 256) W1s[i] = W1[i];
    __syncthreads();
    int ch = t & 63, nl = t >> 6;
    int base = blockIdx.x * 32;
    for (int it = 0; it < 8; ++it) {
        int node = base + it * 4 + nl;
        if (ch < IN_CH) xs[nl][ch] = x[(long)node * IN_CH + ch];
        __syncthreads();
        float acc = 0.0f;
        #pragma unroll
        for (int k = 0; k < IN_CH; ++k)
            acc = fmaf(xs[nl][k], W1s[k * HID + ch], acc);
        g_hs[(long)node * HID + ch] = acc * g_deg[node];
        __syncthreads();
    }
}

// Scatter: agg[dst] += hs[src].  16 lanes per edge, float4 per lane, vector RED.
__global__ void k_scatter(const void* __restrict__ ei) {
    long idx = (long)blockIdx.x * blockDim.x + threadIdx.x;
    if (idx >= (long)N_EDGES * 16) return;
    int e = (int)(idx >> 4);
    int c = (int)(idx & 15);
    int is64 = g_is64;
    int s = load_idx(ei, e, is64);
    int d = load_idx(ei, (long)N_EDGES + e, is64);
    const float4 v = *(const float4*)(g_hs + ((long)s << 6) + (c << 2));
    red_add_v4(g_agg + ((long)d << 6) + (c << 2), v);
}

// Fused layer-2 front half:
//   v    = relu(dinv*(agg + hs) + b1)       (layer-1 output)
//   hs   = (v @ W2) * dinv                  (pre-scaled layer-2 messages, in place)
//   agg  = 0                                (ready for second scatter)
__global__ void k_layer2(const float* __restrict__ b1, const float* __restrict__ W2) {
    __shared__ float W2s[HID * HID];   // 16 KB
    __shared__ float vs[4][HID];
    int t = threadIdx.x;
    for (int i = t; i < HID * HID; i += 256) W2s[i] = W2[i];
    __syncthreads();
    int ch = t & 63, nl = t >> 6;
    int base = blockIdx.x * 32;
    for (int it = 0; it < 8; ++it) {
        int node = base + it * 4 + nl;
        float di = g_deg[node];
        long off = (long)node * HID + ch;
        float a = g_agg[off];
        float h = g_hs[off];
        float v = fmaxf(di * (a + h) + b1[ch], 0.0f);
        vs[nl][ch] = v;
        g_agg[off] = 0.0f;        // re-zero for scatter2
        __syncthreads();
        float acc = 0.0f;
        #pragma unroll 16
        for (int c = 0; c < HID; ++c)
            acc = fmaf(vs[nl][c], W2s[c * HID + ch], acc);
        g_hs[off] = acc * di;     // pre-scaled by dinv for scatter
        __syncthreads();
    }
}

// Finalize layer 2 + pooled sums:  h2 = relu(dinv*(agg+hs)+b2); gsum[batch] += h2.
__global__ void k_final_pool(const float* __restrict__ b2,
                             const void* __restrict__ batch) {
    long idx = (long)blockIdx.x * blockDim.x + threadIdx.x;
    if (idx >= (long)N_NODES * 16) return;
    int node = (int)(idx >> 4);
    int c4   = (int)(idx & 15);
    float di = g_deg[node];
    long off = (long)node * HID + (c4 << 2);
    float4 a = *(const float4*)(g_agg + off);
    float4 h = *(const float4*)(g_hs + off);
    float4 v;
    int cb = c4 << 2;
    v.x = fmaxf(di * (a.x + h.x) + b2[cb + 0], 0.0f);
    v.y = fmaxf(di * (a.y + h.y) + b2[cb + 1], 0.0f);
    v.z = fmaxf(di * (a.z + h.z) + b2[cb + 2], 0.0f);
    v.w = fmaxf(di * (a.w + h.w) + b2[cb + 3], 0.0f);
    int g = load_idx(batch, node, g_is64);
    red_add_v4(g_gsum + (long)g * HID + (c4 << 2), v);
    if (c4 == 0) red_add_f32(&g_gcnt[g], 1.0f);
}

// FC + sigmoid: out[g] = sigmoid((gsum[g]/max(cnt,1)) @ Wfc + bfc)
__global__ void k_fc(const float* __restrict__ Wfc, const float* __restrict__ bfc,
                     float* __restrict__ out) {
    int g = blockIdx.x * blockDim.x + threadIdx.x;
    if (g >= N_GRAPHS) return;
    float inv = 1.0f / fmaxf(g_gcnt[g], 1.0f);
    float acc0 = bfc[0], acc1 = bfc[1], acc2 = bfc[2], acc3 = bfc[3];
    #pragma unroll 8
    for (int c = 0; c < HID; ++c) {
        float m = g_gsum[g * HID + c] * inv;
        acc0 = fmaf(m, Wfc[c * OUT_CH + 0], acc0);
        acc1 = fmaf(m, Wfc[c * OUT_CH + 1], acc1);
        acc2 = fmaf(m, Wfc[c * OUT_CH + 2], acc2);
        acc3 = fmaf(m, Wfc[c * OUT_CH + 3], acc3);
    }
    out[g * OUT_CH + 0] = 1.0f / (1.0f + expf(-acc0));
    out[g * OUT_CH + 1] = 1.0f / (1.0f + expf(-acc1));
    out[g * OUT_CH + 2] = 1.0f / (1.0f + expf(-acc2));
    out[g * OUT_CH + 3] = 1.0f / (1.0f + expf(-acc3));
}

// ---------------- launch ----------------------------------------------------
extern "C" void kernel_launch(void* const* d_in, const int* in_sizes, int n_in,
                              void* d_out, int out_size) {
    const float* x    = (const float*)d_in[0];
    const void*  ei   = d_in[1];              // [2, E], int32 OR int64
    const void*  batch= d_in[2];
    const float* W1   = (const float*)d_in[3];
    const float* b1   = (const float*)d_in[4];
    const float* W2   = (const float*)d_in[5];
    const float* b2   = (const float*)d_in[6];
    const float* Wfc  = (const float*)d_in[7];
    const float* bfc  = (const float*)d_in[8];
    float*       out  = (float*)d_out;

    const int ZB = ((long)N_NODES * HID + 255) / 256;       // 32768
    k_detect<<<1, 32>>>(ei);
    k_zero<<<ZB, 256>>>();
    k_deg<<<(N_EDGES + 255) / 256, 256>>>(ei);
    k_dinv<<<(N_NODES + 255) / 256, 256>>>();
    k_xw1<<<N_NODES / 32, 256>>>(x, W1);
    k_scatter<<<(int)(((long)N_EDGES * 16) / 256), 256>>>(ei);
    k_layer2<<<N_NODES / 32, 256>>>(b1, W2);
    k_scatter<<<(int)(((long)N_EDGES * 16) / 256), 256>>>(ei);
    k_final_pool<<<(int)(((long)N_NODES * 16) / 256), 256>>>(b2, batch);
    k_fc<<<(N_GRAPHS + 255) / 256, 256>>>(Wfc, bfc, out);
}

// round 3
// speedup vs baseline: 2.2747x; 2.2747x over previous
#include <cuda_runtime.h>
#include <cuda_bf16.h>

constexpr int N_NODES  = 131072;
constexpr int N_EDGES  = 2097152;
constexpr int N_GRAPHS = 2048;
constexpr int HID      = 64;
constexpr int IN_CH    = 12;
constexpr int OUT_CH   = 4;

// ---------------- scratch (device globals; no allocation allowed) ----------
__device__ float g_hs [N_NODES * HID];    // per-layer messages (pre-scaled by dinv)
__device__ float g_v  [N_NODES * HID];    // layer-1 activations
__device__ float g_dinv[N_NODES];         // rsqrt(deg+1)
__device__ int   g_degi[N_NODES];         // integer in-degree
__device__ int   g_rowptr[N_NODES + 1];   // CSR row pointers (dst-sorted)
__device__ int   g_fill[N_NODES];         // fill cursors
__device__ int   g_bsum[128];             // scan block sums
__device__ int   g_csr[N_EDGES];          // CSR column (src) indices
__device__ float g_gsum[N_GRAPHS * HID];  // pooled sums
__device__ float g_gcnt[N_GRAPHS];        // pooled counts
__device__ int   g_is64;                  // index dtype flag

// ---------------- helpers --------------------------------------------------
__device__ __forceinline__ void red_add_v2(float* p, float2 v) {
    asm volatile("red.global.add.v2.f32 [%0], {%1,%2};"
                 :: "l"(p), "f"(v.x), "f"(v.y) : "memory");
}
__device__ __forceinline__ void red_add_f32(float* p, float v) {
    asm volatile("red.global.add.f32 [%0], %1;" :: "l"(p), "f"(v) : "memory");
}
__device__ __forceinline__ int load_idx(const void* p, long i, int is64) {
    return is64 ? (int)((const long long*)p)[i] : ((const int*)p)[i];
}

// ---------------- kernels --------------------------------------------------

// Detect int32 vs int64 indices: int64 values < 2^32 have all-zero high words.
__global__ void k_detect(const void* __restrict__ ei) {
    if (threadIdx.x != 0 || blockIdx.x != 0) return;
    const int* p = (const int*)ei;
    int nz = 0;
    #pragma unroll 8
    for (int i = 0; i < 512; ++i) nz += (p[2 * i + 1] != 0);
    g_is64 = (nz == 0) ? 1 : 0;
}

__global__ void k_zero() {
    int i = blockIdx.x * blockDim.x + threadIdx.x;
    if (i < N_NODES)         g_degi[i] = 0;
    if (i < N_GRAPHS * HID)  g_gsum[i] = 0.0f;
    if (i < N_GRAPHS)        g_gcnt[i] = 0.0f;
}

// In-degree at dst.
__global__ void k_deg(const void* __restrict__ ei) {
    int e = blockIdx.x * blockDim.x + threadIdx.x;
    if (e >= N_EDGES) return;
    int d = load_idx(ei, (long)N_EDGES + e, g_is64);
    atomicAdd(&g_degi[d], 1);
}

// Exclusive scan over g_degi, stage 1: per-block (1024 elems) partial scans.
__global__ void k_scan1() {
    __shared__ int s[256];
    int t = threadIdx.x;
    int base = blockIdx.x * 1024 + t * 4;
    int v0 = g_degi[base + 0], v1 = g_degi[base + 1];
    int v2 = g_degi[base + 2], v3 = g_degi[base + 3];
    int tsum = v0 + v1 + v2 + v3;
    s[t] = tsum;
    __syncthreads();
    #pragma unroll
    for (int off = 1; off < 256; off <<= 1) {
        int x = (t >= off) ? s[t - off] : 0;
        __syncthreads();
        s[t] += x;
        __syncthreads();
    }
    int excl = s[t] - tsum;
    g_rowptr[base + 0] = excl;
    g_rowptr[base + 1] = excl + v0;
    g_rowptr[base + 2] = excl + v0 + v1;
    g_rowptr[base + 3] = excl + v0 + v1 + v2;
    if (t == 255) g_bsum[blockIdx.x] = s[255];
}

// Stage 2: exclusive scan of the 128 block sums (single block).
__global__ void k_scan2() {
    __shared__ int s[128];
    int t = threadIdx.x;
    int v = g_bsum[t];
    s[t] = v;
    __syncthreads();
    #pragma unroll
    for (int off = 1; off < 128; off <<= 1) {
        int x = (t >= off) ? s[t - off] : 0;
        __syncthreads();
        s[t] += x;
        __syncthreads();
    }
    g_bsum[t] = s[t] - v;   // exclusive
}

// Stage 3: add block offsets, init fill cursors, finalize rowptr, compute dinv.
__global__ void k_scan3() {
    int i = blockIdx.x * blockDim.x + threadIdx.x;
    if (i >= N_NODES) return;
    int r = g_rowptr[i] + g_bsum[i >> 10];
    g_rowptr[i] = r;
    g_fill[i]   = r;
    g_dinv[i]   = rsqrtf((float)g_degi[i] + 1.0f);
    if (i == 0) g_rowptr[N_NODES] = N_EDGES;
}

// Fill CSR: g_csr[pos(dst)] = src.
__global__ void k_fill(const void* __restrict__ ei) {
    int e = blockIdx.x * blockDim.x + threadIdx.x;
    if (e >= N_EDGES) return;
    int is64 = g_is64;
    int s = load_idx(ei, e, is64);
    int d = load_idx(ei, (long)N_EDGES + e, is64);
    int pos = atomicAdd(&g_fill[d], 1);
    g_csr[pos] = s;
}

// hs = (x @ W1) * dinv.
__global__ void k_xw1(const float* __restrict__ x, const float* __restrict__ W1) {
    __shared__ float W1s[IN_CH * HID];
    __shared__ float xs[4][IN_CH];
    int t = threadIdx.x;
    for (int i = t; i < IN_CH * HID; i += 256) W1s[i] = W1[i];
    __syncthreads();
    int ch = t & 63, nl = t >> 6;
    int base = blockIdx.x * 32;
    for (int it = 0; it < 8; ++it) {
        int node = base + it * 4 + nl;
        if (ch < IN_CH) xs[nl][ch] = x[(long)node * IN_CH + ch];
        __syncthreads();
        float acc = 0.0f;
        #pragma unroll
        for (int k = 0; k < IN_CH; ++k)
            acc = fmaf(xs[nl][k], W1s[k * HID + ch], acc);
        g_hs[(long)node * HID + ch] = acc * g_dinv[node];
        __syncthreads();
    }
}

// Warp-per-node CSR gather + elementwise epilogue.
// FINAL=0: v = relu(dinv*(sum + self) + b)  -> g_v
// FINAL=1: h2 = relu(...)                   -> pooled RED into gsum/gcnt
template<int FINAL>
__global__ void k_gather(const float* __restrict__ b,
                         const void* __restrict__ batch) {
    int warp = (blockIdx.x * blockDim.x + threadIdx.x) >> 5;
    int lane = threadIdx.x & 31;
    if (warp >= N_NODES) return;
    int d = warp;
    int start = g_rowptr[d];
    int end   = g_rowptr[d + 1];
    float2 acc = make_float2(0.0f, 0.0f);
    for (int i = start; i < end; i += 32) {
        int n = end - i;
        int sidx = (lane < n) ? g_csr[i + lane] : 0;
        int m = n < 32 ? n : 32;
        #pragma unroll 4
        for (int j = 0; j < m; ++j) {
            int s = __shfl_sync(0xFFFFFFFFu, sidx, j);
            float2 vv = *(const float2*)(g_hs + ((long)s << 6) + (lane << 1));
            acc.x += vv.x;
            acc.y += vv.y;
        }
    }
    float di = g_dinv[d];
    float2 self = *(const float2*)(g_hs + ((long)d << 6) + (lane << 1));
    float2 bb = ((const float2*)b)[lane];
    float2 r;
    r.x = fmaxf(di * (acc.x + self.x) + bb.x, 0.0f);
    r.y = fmaxf(di * (acc.y + self.y) + bb.y, 0.0f);
    if (FINAL) {
        int g = load_idx(batch, d, g_is64);
        red_add_v2(g_gsum + ((long)g << 6) + (lane << 1), r);
        if (lane == 0) red_add_f32(&g_gcnt[g], 1.0f);
    } else {
        *(float2*)(g_v + ((long)d << 6) + (lane << 1)) = r;
    }
}

// hs = (v @ W2) * dinv.
__global__ void k_layer2m(const float* __restrict__ W2) {
    __shared__ float W2s[HID * HID];
    __shared__ float vs[4][HID];
    int t = threadIdx.x;
    for (int i = t; i < HID * HID; i += 256) W2s[i] = W2[i];
    __syncthreads();
    int ch = t & 63, nl = t >> 6;
    int base = blockIdx.x * 32;
    for (int it = 0; it < 8; ++it) {
        int node = base + it * 4 + nl;
        long off = (long)node * HID + ch;
        vs[nl][ch] = g_v[off];
        __syncthreads();
        float acc = 0.0f;
        #pragma unroll 16
        for (int c = 0; c < HID; ++c)
            acc = fmaf(vs[nl][c], W2s[c * HID + ch], acc);
        g_hs[off] = acc * g_dinv[node];
        __syncthreads();
    }
}

// FC + sigmoid.
__global__ void k_fc(const float* __restrict__ Wfc, const float* __restrict__ bfc,
                     float* __restrict__ out) {
    int g = blockIdx.x * blockDim.x + threadIdx.x;
    if (g >= N_GRAPHS) return;
    float inv = 1.0f / fmaxf(g_gcnt[g], 1.0f);
    float acc0 = bfc[0], acc1 = bfc[1], acc2 = bfc[2], acc3 = bfc[3];
    #pragma unroll 8
    for (int c = 0; c < HID; ++c) {
        float m = g_gsum[g * HID + c] * inv;
        acc0 = fmaf(m, Wfc[c * OUT_CH + 0], acc0);
        acc1 = fmaf(m, Wfc[c * OUT_CH + 1], acc1);
        acc2 = fmaf(m, Wfc[c * OUT_CH + 2], acc2);
        acc3 = fmaf(m, Wfc[c * OUT_CH + 3], acc3);
    }
    out[g * OUT_CH + 0] = 1.0f / (1.0f + expf(-acc0));
    out[g * OUT_CH + 1] = 1.0f / (1.0f + expf(-acc1));
    out[g * OUT_CH + 2] = 1.0f / (1.0f + expf(-acc2));
    out[g * OUT_CH + 3] = 1.0f / (1.0f + expf(-acc3));
}

// ---------------- launch ----------------------------------------------------
extern "C" void kernel_launch(void* const* d_in, const int* in_sizes, int n_in,
                              void* d_out, int out_size) {
    const float* x    = (const float*)d_in[0];
    const void*  ei   = d_in[1];
    const void*  batch= d_in[2];
    const float* W1   = (const float*)d_in[3];
    const float* b1   = (const float*)d_in[4];
    const float* W2   = (const float*)d_in[5];
    const float* b2   = (const float*)d_in[6];
    const float* Wfc  = (const float*)d_in[7];
    const float* bfc  = (const float*)d_in[8];
    float*       out  = (float*)d_out;

    k_detect<<<1, 32>>>(ei);
    k_zero<<<(N_NODES + 255) / 256, 256>>>();
    k_deg<<<(N_EDGES + 255) / 256, 256>>>(ei);
    k_scan1<<<128, 256>>>();
    k_scan2<<<1, 128>>>();
    k_scan3<<<(N_NODES + 255) / 256, 256>>>();
    k_fill<<<(N_EDGES + 255) / 256, 256>>>(ei);
    k_xw1<<<N_NODES / 32, 256>>>(x, W1);
    k_gather<0><<<N_NODES / 8, 256>>>(b1, batch);
    k_layer2m<<<N_NODES / 32, 256>>>(W2);
    k_gather<1><<<N_NODES / 8, 256>>>(b2, batch);
    k_fc<<<(N_GRAPHS + 255) / 256, 256>>>(Wfc, bfc, out);
}

// round 6
// speedup vs baseline: 2.5916x; 1.1393x over previous
#include <cuda_runtime.h>
#include <cuda_fp16.h>

constexpr int N_NODES  = 131072;
constexpr int N_EDGES  = 2097152;
constexpr int N_GRAPHS = 2048;
constexpr int HID      = 64;
constexpr int IN_CH    = 12;
constexpr int OUT_CH   = 4;

// ---------------- scratch (device globals; no allocation allowed) ----------
__device__ __half g_hs[N_NODES * HID];    // messages, fp16, pre-scaled by dinv
__device__ float  g_v  [N_NODES * HID];   // layer-1 activations (fp32)
__device__ float  g_dinv[N_NODES];        // rsqrt(deg+1)
__device__ int    g_degi[N_NODES];        // integer in-degree
__device__ int    g_rowptr[N_NODES + 1];  // CSR row pointers (dst-sorted)
__device__ int    g_fill[N_NODES];        // fill cursors
__device__ int    g_bsum[128];            // scan block sums
__device__ int    g_csr[N_EDGES];         // CSR column (src) indices
__device__ float  g_gsum[N_GRAPHS * HID]; // pooled sums
__device__ float  g_gcnt[N_GRAPHS];       // pooled counts
__device__ int    g_is64;                 // index dtype flag

// ---------------- helpers --------------------------------------------------
__device__ __forceinline__ void red_add_v2(float* p, float2 v) {
    asm volatile("red.global.add.v2.f32 [%0], {%1,%2};"
                 :: "l"(p), "f"(v.x), "f"(v.y) : "memory");
}
__device__ __forceinline__ void red_add_f32(float* p, float v) {
    asm volatile("red.global.add.f32 [%0], %1;" :: "l"(p), "f"(v) : "memory");
}
__device__ __forceinline__ int load_idx(const void* p, long i, int is64) {
    return is64 ? (int)((const long long*)p)[i] : ((const int*)p)[i];
}

// ---------------- kernels --------------------------------------------------

// Init: zero accumulators; block 0 also detects index dtype (int64 values
// < 2^32 have all-zero high 32-bit words; int32 data has random words there).
__global__ void k_init(const void* __restrict__ ei) {
    int i = blockIdx.x * blockDim.x + threadIdx.x;
    if (i < N_NODES)         g_degi[i] = 0;
    if (i < N_GRAPHS * HID)  g_gsum[i] = 0.0f;
    if (i < N_GRAPHS)        g_gcnt[i] = 0.0f;
    if (i == 0) {
        const int* p = (const int*)ei;
        int nz = 0;
        #pragma unroll 8
        for (int k = 0; k < 512; ++k) nz += (p[2 * k + 1] != 0);
        g_is64 = (nz == 0) ? 1 : 0;
    }
}

// In-degree at dst.
__global__ void k_deg(const void* __restrict__ ei) {
    int e = blockIdx.x * blockDim.x + threadIdx.x;
    if (e >= N_EDGES) return;
    int d = load_idx(ei, (long)N_EDGES + e, g_is64);
    atomicAdd(&g_degi[d], 1);
}

// Exclusive scan over g_degi, stage 1: per-block (1024 elems) partial scans.
__global__ void k_scan1() {
    __shared__ int s[256];
    int t = threadIdx.x;
    int base = blockIdx.x * 1024 + t * 4;
    int v0 = g_degi[base + 0], v1 = g_degi[base + 1];
    int v2 = g_degi[base + 2], v3 = g_degi[base + 3];
    int tsum = v0 + v1 + v2 + v3;
    s[t] = tsum;
    __syncthreads();
    #pragma unroll
    for (int off = 1; off < 256; off <<= 1) {
        int x = (t >= off) ? s[t - off] : 0;
        __syncthreads();
        s[t] += x;
        __syncthreads();
    }
    int excl = s[t] - tsum;
    g_rowptr[base + 0] = excl;
    g_rowptr[base + 1] = excl + v0;
    g_rowptr[base + 2] = excl + v0 + v1;
    g_rowptr[base + 3] = excl + v0 + v1 + v2;
    if (t == 255) g_bsum[blockIdx.x] = s[255];
}

// Stage 2: exclusive scan of the 128 block sums (single block).
__global__ void k_scan2() {
    __shared__ int s[128];
    int t = threadIdx.x;
    int v = g_bsum[t];
    s[t] = v;
    __syncthreads();
    #pragma unroll
    for (int off = 1; off < 128; off <<= 1) {
        int x = (t >= off) ? s[t - off] : 0;
        __syncthreads();
        s[t] += x;
        __syncthreads();
    }
    g_bsum[t] = s[t] - v;   // exclusive
}

// Stage 3: add block offsets, init fill cursors, finalize rowptr, compute dinv.
__global__ void k_scan3() {
    int i = blockIdx.x * blockDim.x + threadIdx.x;
    if (i >= N_NODES) return;
    int r = g_rowptr[i] + g_bsum[i >> 10];
    g_rowptr[i] = r;
    g_fill[i]   = r;
    g_dinv[i]   = rsqrtf((float)g_degi[i] + 1.0f);
    if (i == 0) g_rowptr[N_NODES] = N_EDGES;
}

// Fill CSR: g_csr[pos(dst)] = src.
__global__ void k_fill(const void* __restrict__ ei) {
    int e = blockIdx.x * blockDim.x + threadIdx.x;
    if (e >= N_EDGES) return;
    int is64 = g_is64;
    int s = load_idx(ei, e, is64);
    int d = load_idx(ei, (long)N_EDGES + e, is64);
    int pos = atomicAdd(&g_fill[d], 1);
    g_csr[pos] = s;
}

// hs = half2((x @ W1) * dinv). 32 lanes/node, 2 channels/lane, 8 nodes/iter.
__global__ void k_xw1(const float* __restrict__ x, const float* __restrict__ W1) {
    __shared__ float W1s[IN_CH * HID];
    __shared__ float xs[8][IN_CH];
    int t = threadIdx.x;
    for (int i = t; i < IN_CH * HID; i += 256) W1s[i] = W1[i];
    int lane = t & 31, nl = t >> 5;
    int base = blockIdx.x * 32;
    __syncthreads();
    for (int it = 0; it < 4; ++it) {
        int node = base + it * 8 + nl;
        if (lane < IN_CH) xs[nl][lane] = x[(long)node * IN_CH + lane];
        __syncthreads();
        float acc0 = 0.0f, acc1 = 0.0f;
        #pragma unroll
        for (int k = 0; k < IN_CH; ++k) {
            float xv = xs[nl][k];
            float2 w = *(const float2*)(W1s + k * HID + (lane << 1));
            acc0 = fmaf(xv, w.x, acc0);
            acc1 = fmaf(xv, w.y, acc1);
        }
        float di = g_dinv[node];
        ((__half2*)g_hs)[((long)node << 5) + lane] =
            __floats2half2_rn(acc0 * di, acc1 * di);
        __syncthreads();
    }
}

// Warp-per-node CSR gather (fp16 rows, fp32 accumulate) + epilogue.
// FINAL=0: v = relu(dinv*(sum+self)+b) -> g_v (fp32)
// FINAL=1: h2 = relu(...)              -> pooled RED into gsum/gcnt
template<int FINAL>
__global__ void k_gather(const float* __restrict__ b,
                         const void* __restrict__ batch) {
    int warp = (blockIdx.x * blockDim.x + threadIdx.x) >> 5;
    int lane = threadIdx.x & 31;
    if (warp >= N_NODES) return;
    int start = g_rowptr[warp];
    int end   = g_rowptr[warp + 1];
    const __half2* hp = (const __half2*)g_hs;
    float2 acc = make_float2(0.0f, 0.0f);
    for (int i = start; i < end; i += 32) {
        int n = end - i;
        int sidx = (lane < n) ? g_csr[i + lane] : 0;
        int m = n < 32 ? n : 32;
        #pragma unroll 4
        for (int j = 0; j < m; ++j) {
            int s = __shfl_sync(0xFFFFFFFFu, sidx, j);
            float2 vv = __half22float2(hp[((long)s << 5) + lane]);
            acc.x += vv.x;
            acc.y += vv.y;
        }
    }
    float di = g_dinv[warp];
    float2 self = __half22float2(hp[((long)warp << 5) + lane]);
    float2 bb = ((const float2*)b)[lane];
    float2 r;
    r.x = fmaxf(di * (acc.x + self.x) + bb.x, 0.0f);
    r.y = fmaxf(di * (acc.y + self.y) + bb.y, 0.0f);
    if (FINAL) {
        int g = load_idx(batch, warp, g_is64);
        red_add_v2(g_gsum + ((long)g << 6) + (lane << 1), r);
        if (lane == 0) red_add_f32(&g_gcnt[g], 1.0f);
    } else {
        *(float2*)(g_v + ((long)warp << 6) + (lane << 1)) = r;
    }
}

// hs = half2((v @ W2) * dinv). 32 lanes/node, 2 channels/lane.
__global__ void k_layer2m(const float* __restrict__ W2) {
    __shared__ float W2s[HID * HID];   // 16 KB
    __shared__ float vs[8][HID];
    int t = threadIdx.x;
    for (int i = t; i < HID * HID; i += 256) W2s[i] = W2[i];
    int lane = t & 31, nl = t >> 5;
    int base = blockIdx.x * 32;
    __syncthreads();
    for (int it = 0; it < 4; ++it) {
        int node = base + it * 8 + nl;
        float2 vv = *(const float2*)(g_v + ((long)node << 6) + (lane << 1));
        vs[nl][2 * lane]     = vv.x;
        vs[nl][2 * lane + 1] = vv.y;
        __syncthreads();
        float acc0 = 0.0f, acc1 = 0.0f;
        #pragma unroll
        for (int c = 0; c < HID; ++c) {
            float v = vs[nl][c];
            float2 w = *(const float2*)(W2s + c * HID + (lane << 1));
            acc0 = fmaf(v, w.x, acc0);
            acc1 = fmaf(v, w.y, acc1);
        }
        float di = g_dinv[node];
        ((__half2*)g_hs)[((long)node << 5) + lane] =
            __floats2half2_rn(acc0 * di, acc1 * di);
        __syncthreads();
    }
}

// FC + sigmoid.
__global__ void k_fc(const float* __restrict__ Wfc, const float* __restrict__ bfc,
                     float* __restrict__ out) {
    int g = blockIdx.x * blockDim.x + threadIdx.x;
    if (g >= N_GRAPHS) return;
    float inv = 1.0f / fmaxf(g_gcnt[g], 1.0f);
    float acc0 = bfc[0], acc1 = bfc[1], acc2 = bfc[2], acc3 = bfc[3];
    #pragma unroll 8
    for (int c = 0; c < HID; ++c) {
        float m = g_gsum[g * HID + c] * inv;
        acc0 = fmaf(m, Wfc[c * OUT_CH + 0], acc0);
        acc1 = fmaf(m, Wfc[c * OUT_CH + 1], acc1);
        acc2 = fmaf(m, Wfc[c * OUT_CH + 2], acc2);
        acc3 = fmaf(m, Wfc[c * OUT_CH + 3], acc3);
    }
    out[g * OUT_CH + 0] = 1.0f / (1.0f + expf(-acc0));
    out[g * OUT_CH + 1] = 1.0f / (1.0f + expf(-acc1));
    out[g * OUT_CH + 2] = 1.0f / (1.0f + expf(-acc2));
    out[g * OUT_CH + 3] = 1.0f / (1.0f + expf(-acc3));
}

// ---------------- launch ----------------------------------------------------
extern "C" void kernel_launch(void* const* d_in, const int* in_sizes, int n_in,
                              void* d_out, int out_size) {
    const float* x    = (const float*)d_in[0];
    const void*  ei   = d_in[1];
    const void*  batch= d_in[2];
    const float* W1   = (const float*)d_in[3];
    const float* b1   = (const float*)d_in[4];
    const float* W2   = (const float*)d_in[5];
    const float* b2   = (const float*)d_in[6];
    const float* Wfc  = (const float*)d_in[7];
    const float* bfc  = (const float*)d_in[8];
    float*       out  = (float*)d_out;

    k_init<<<(N_NODES + 255) / 256, 256>>>(ei);
    k_deg<<<(N_EDGES + 255) / 256, 256>>>(ei);
    k_scan1<<<128, 256>>>();
    k_scan2<<<1, 128>>>();
    k_scan3<<<(N_NODES + 255) / 256, 256>>>();
    k_fill<<<(N_EDGES + 255) / 256, 256>>>(ei);
    k_xw1<<<N_NODES / 32, 256>>>(x, W1);
    k_gather<0><<<N_NODES / 8, 256>>>(b1, batch);
    k_layer2m<<<N_NODES / 32, 256>>>(W2);
    k_gather<1><<<N_NODES / 8, 256>>>(b2, batch);
    k_fc<<<(N_GRAPHS + 255) / 256, 256>>>(Wfc, bfc, out);
}

// round 7
// speedup vs baseline: 3.2416x; 1.2508x over previous
#include <cuda_runtime.h>
#include <cuda_fp16.h>

constexpr int N_NODES  = 131072;
constexpr int N_EDGES  = 2097152;
constexpr int N_GRAPHS = 2048;
constexpr int HID      = 64;
constexpr int IN_CH    = 12;
constexpr int OUT_CH   = 4;

// ---------------- scratch (device globals; statically zero-initialized) ----
// State discipline: every run leaves degi/gsum/gcnt re-zeroed (self-restoring),
// so graph replays are deterministic without an init kernel.
__device__ __half g_hs[N_NODES * HID];    // messages, fp16, pre-scaled by dinv
__device__ float  g_v  [N_NODES * HID];   // layer-1 activations (fp32)
__device__ float  g_dinv[N_NODES];        // rsqrt(deg+1)
__device__ int    g_degi[N_NODES];        // in-degree (re-zeroed by k_scan1)
__device__ int    g_rowptr[N_NODES + 1];  // CSR row pointers (dst-sorted)
__device__ int    g_fill[N_NODES];        // fill cursors
__device__ int    g_bsum[128];            // scan block sums
__device__ int    g_csr[N_EDGES];         // CSR column (src) indices
__device__ float  g_gsum[N_GRAPHS * HID]; // pooled sums (re-zeroed by k_fc)
__device__ float  g_gcnt[N_GRAPHS];       // pooled counts (re-zeroed by k_fc)
__device__ int    g_is64;                 // index dtype flag

// ---------------- helpers --------------------------------------------------
__device__ __forceinline__ void red_add_v4(float* p, float4 v) {
    asm volatile("red.global.add.v4.f32 [%0], {%1,%2,%3,%4};"
                 :: "l"(p), "f"(v.x), "f"(v.y), "f"(v.z), "f"(v.w) : "memory");
}
__device__ __forceinline__ void red_add_f32(float* p, float v) {
    asm volatile("red.global.add.f32 [%0], %1;" :: "l"(p), "f"(v) : "memory");
}
__device__ __forceinline__ int load_idx(const void* p, long i, int is64) {
    return is64 ? (int)((const long long*)p)[i] : ((const int*)p)[i];
}

// ---------------- kernels --------------------------------------------------

// Detect int32 vs int64 indices: int64 values < 2^32 have all-zero high words.
__global__ void k_detect(const void* __restrict__ ei) {
    const int* p = (const int*)ei;
    int lane = threadIdx.x & 31;
    int nz = 0;
    #pragma unroll
    for (int k = 0; k < 16; ++k) nz += (p[2 * (lane * 16 + k) + 1] != 0);
    unsigned any = __ballot_sync(0xFFFFFFFFu, nz != 0);
    if (lane == 0) g_is64 = (any == 0) ? 1 : 0;
}

// In-degree at dst.
__global__ void k_deg(const void* __restrict__ ei) {
    int e = blockIdx.x * blockDim.x + threadIdx.x;
    if (e >= N_EDGES) return;
    int d = load_idx(ei, (long)N_EDGES + e, g_is64);
    atomicAdd(&g_degi[d], 1);
}

// Scan stage 1: per-block (1024 elems) partial scans; also computes dinv and
// re-zeroes degi for the next replay.
__global__ void k_scan1() {
    __shared__ int s[256];
    int t = threadIdx.x;
    int base = blockIdx.x * 1024 + t * 4;
    int v0 = g_degi[base + 0], v1 = g_degi[base + 1];
    int v2 = g_degi[base + 2], v3 = g_degi[base + 3];
    g_degi[base + 0] = 0; g_degi[base + 1] = 0;
    g_degi[base + 2] = 0; g_degi[base + 3] = 0;
    g_dinv[base + 0] = rsqrtf((float)v0 + 1.0f);
    g_dinv[base + 1] = rsqrtf((float)v1 + 1.0f);
    g_dinv[base + 2] = rsqrtf((float)v2 + 1.0f);
    g_dinv[base + 3] = rsqrtf((float)v3 + 1.0f);
    int tsum = v0 + v1 + v2 + v3;
    s[t] = tsum;
    __syncthreads();
    #pragma unroll
    for (int off = 1; off < 256; off <<= 1) {
        int x = (t >= off) ? s[t - off] : 0;
        __syncthreads();
        s[t] += x;
        __syncthreads();
    }
    int excl = s[t] - tsum;
    g_rowptr[base + 0] = excl;
    g_rowptr[base + 1] = excl + v0;
    g_rowptr[base + 2] = excl + v0 + v1;
    g_rowptr[base + 3] = excl + v0 + v1 + v2;
    if (t == 255) g_bsum[blockIdx.x] = s[255];
}

// Scan stage 2+3 fused: every block redundantly scans the 128 block sums in
// shared memory, then adds offsets, finalizes rowptr and fill cursors.
__global__ void k_scan3() {
    __shared__ int s[128];
    int t = threadIdx.x;
    if (t < 128) s[t] = g_bsum[t];
    __syncthreads();
    // Hillis-Steele inclusive scan on threads 0..127
    #pragma unroll
    for (int off = 1; off < 128; off <<= 1) {
        int x = 0;
        if (t < 128 && t >= off) x = s[t - off];
        __syncthreads();
        if (t < 128) s[t] += x;
        __syncthreads();
    }
    int i = blockIdx.x * blockDim.x + t;
    int blk = i >> 10;
    int boff = (blk == 0) ? 0 : s[blk - 1];   // exclusive
    int r = g_rowptr[i] + boff;
    g_rowptr[i] = r;
    g_fill[i]   = r;
    if (i == 0) g_rowptr[N_NODES] = N_EDGES;
}

// Combined: blocks [0,8192) fill CSR; blocks [8192,12288) compute xw1.
__global__ void k_fill_xw1(const void* __restrict__ ei,
                           const float* __restrict__ x,
                           const float* __restrict__ W1) {
    if (blockIdx.x < 8192) {
        int e = blockIdx.x * 256 + threadIdx.x;
        int is64 = g_is64;
        int s = load_idx(ei, e, is64);
        int d = load_idx(ei, (long)N_EDGES + e, is64);
        int pos = atomicAdd(&g_fill[d], 1);
        g_csr[pos] = s;
    } else {
        __shared__ float W1s[IN_CH * HID];
        __shared__ float xs[8][IN_CH];
        int t = threadIdx.x;
        for (int i = t; i < IN_CH * HID; i += 256) W1s[i] = W1[i];
        int lane = t & 31, nl = t >> 5;
        int base = (blockIdx.x - 8192) * 32;
        __syncthreads();
        for (int it = 0; it < 4; ++it) {
            int node = base + it * 8 + nl;
            if (lane < IN_CH) xs[nl][lane] = x[(long)node * IN_CH + lane];
            __syncthreads();
            float acc0 = 0.0f, acc1 = 0.0f;
            #pragma unroll
            for (int k = 0; k < IN_CH; ++k) {
                float xv = xs[nl][k];
                float2 w = *(const float2*)(W1s + k * HID + (lane << 1));
                acc0 = fmaf(xv, w.x, acc0);
                acc1 = fmaf(xv, w.y, acc1);
            }
            float di = g_dinv[node];
            ((__half2*)g_hs)[((long)node << 5) + lane] =
                __floats2half2_rn(acc0 * di, acc1 * di);
            __syncthreads();
        }
    }
}

// CSR gather: 4 nodes per warp, 8 lanes per node, int4 (16B) per lane.
// fp16 HADD2 accumulation; fp32 epilogue.
// FINAL=0: v = relu(dinv*(sum+self)+b) -> g_v (fp32)
// FINAL=1: h2 = relu(...)              -> pooled RED into gsum/gcnt
template<int FINAL>
__global__ void k_gather(const float* __restrict__ b,
                         const void* __restrict__ batch) {
    int warp = (blockIdx.x * blockDim.x + threadIdx.x) >> 5;
    int lane = threadIdx.x & 31;
    int li   = lane & 7;                 // lane within 8-lane group
    int node = warp * 4 + (lane >> 3);
    int start = g_rowptr[node];
    int deg   = g_rowptr[node + 1] - start;
    const int4* rows = (const int4*)g_hs;   // 8 int4 per 128B row
    __half2 zero = __float2half2_rn(0.0f);
    __half2 acc0 = zero, acc1 = zero, acc2 = zero, acc3 = zero;
    for (int off = 0; __any_sync(0xFFFFFFFFu, off < deg); off += 8) {
        int rel = off + li;
        int sidx = (rel < deg) ? g_csr[start + rel] : -1;
        #pragma unroll
        for (int j = 0; j < 8; ++j) {
            int s = __shfl_sync(0xFFFFFFFFu, sidx, j, 8);
            if (s >= 0) {
                int4 v = rows[((long)s << 3) + li];
                const __half2* hv = (const __half2*)&v;
                acc0 = __hadd2(acc0, hv[0]);
                acc1 = __hadd2(acc1, hv[1]);
                acc2 = __hadd2(acc2, hv[2]);
                acc3 = __hadd2(acc3, hv[3]);
            }
        }
    }
    float di = g_dinv[node];
    int4 sv = rows[((long)node << 3) + li];
    const __half2* sh = (const __half2*)&sv;
    float4 bA = ((const float4*)b)[li * 2];
    float4 bB = ((const float4*)b)[li * 2 + 1];
    float2 a0 = __half22float2(acc0), s0 = __half22float2(sh[0]);
    float2 a1 = __half22float2(acc1), s1 = __half22float2(sh[1]);
    float2 a2 = __half22float2(acc2), s2 = __half22float2(sh[2]);
    float2 a3 = __half22float2(acc3), s3 = __half22float2(sh[3]);
    float4 o1, o2;
    o1.x = fmaxf(di * (a0.x + s0.x) + bA.x, 0.0f);
    o1.y = fmaxf(di * (a0.y + s0.y) + bA.y, 0.0f);
    o1.z = fmaxf(di * (a1.x + s1.x) + bA.z, 0.0f);
    o1.w = fmaxf(di * (a1.y + s1.y) + bA.w, 0.0f);
    o2.x = fmaxf(di * (a2.x + s2.x) + bB.x, 0.0f);
    o2.y = fmaxf(di * (a2.y + s2.y) + bB.y, 0.0f);
    o2.z = fmaxf(di * (a3.x + s3.x) + bB.z, 0.0f);
    o2.w = fmaxf(di * (a3.y + s3.y) + bB.w, 0.0f);
    if (FINAL) {
        int g = load_idx(batch, node, g_is64);
        float* gp = g_gsum + ((long)g << 6) + (li << 3);
        red_add_v4(gp, o1);
        red_add_v4(gp + 4, o2);
        if (li == 0) red_add_f32(&g_gcnt[g], 1.0f);
    } else {
        float4* vp = (float4*)(g_v + ((long)node << 6) + (li << 3));
        vp[0] = o1;
        vp[1] = o2;
    }
}

// hs = half2((v @ W2) * dinv). 64 nodes/block to amortize the W2 smem fill.
__global__ void k_layer2m(const float* __restrict__ W2) {
    __shared__ float W2s[HID * HID];   // 16 KB
    __shared__ float vs[8][HID];
    int t = threadIdx.x;
    for (int i = t; i < HID * HID; i += 256) W2s[i] = W2[i];
    int lane = t & 31, nl = t >> 5;
    int base = blockIdx.x * 64;
    __syncthreads();
    for (int it = 0; it < 8; ++it) {
        int node = base + it * 8 + nl;
        float2 vv = *(const float2*)(g_v + ((long)node << 6) + (lane << 1));
        vs[nl][2 * lane]     = vv.x;
        vs[nl][2 * lane + 1] = vv.y;
        __syncthreads();
        float acc0 = 0.0f, acc1 = 0.0f;
        #pragma unroll
        for (int c = 0; c < HID; ++c) {
            float v = vs[nl][c];
            float2 w = *(const float2*)(W2s + c * HID + (lane << 1));
            acc0 = fmaf(v, w.x, acc0);
            acc1 = fmaf(v, w.y, acc1);
        }
        float di = g_dinv[node];
        ((__half2*)g_hs)[((long)node << 5) + lane] =
            __floats2half2_rn(acc0 * di, acc1 * di);
        __syncthreads();
    }
}

// FC + sigmoid; re-zeroes gsum/gcnt for the next replay.
__global__ void k_fc(const float* __restrict__ Wfc, const float* __restrict__ bfc,
                     float* __restrict__ out) {
    int g = blockIdx.x * blockDim.x + threadIdx.x;
    if (g >= N_GRAPHS) return;
    float cnt = g_gcnt[g];
    g_gcnt[g] = 0.0f;
    float inv = 1.0f / fmaxf(cnt, 1.0f);
    float acc0 = bfc[0], acc1 = bfc[1], acc2 = bfc[2], acc3 = bfc[3];
    #pragma unroll 8
    for (int c = 0; c < HID; ++c) {
        float m = g_gsum[g * HID + c] * inv;
        g_gsum[g * HID + c] = 0.0f;
        acc0 = fmaf(m, Wfc[c * OUT_CH + 0], acc0);
        acc1 = fmaf(m, Wfc[c * OUT_CH + 1], acc1);
        acc2 = fmaf(m, Wfc[c * OUT_CH + 2], acc2);
        acc3 = fmaf(m, Wfc[c * OUT_CH + 3], acc3);
    }
    out[g * OUT_CH + 0] = 1.0f / (1.0f + expf(-acc0));
    out[g * OUT_CH + 1] = 1.0f / (1.0f + expf(-acc1));
    out[g * OUT_CH + 2] = 1.0f / (1.0f + expf(-acc2));
    out[g * OUT_CH + 3] = 1.0f / (1.0f + expf(-acc3));
}

// ---------------- launch ----------------------------------------------------
extern "C" void kernel_launch(void* const* d_in, const int* in_sizes, int n_in,
                              void* d_out, int out_size) {
    const float* x    = (const float*)d_in[0];
    const void*  ei   = d_in[1];
    const void*  batch= d_in[2];
    const float* W1   = (const float*)d_in[3];
    const float* b1   = (const float*)d_in[4];
    const float* W2   = (const float*)d_in[5];
    const float* b2   = (const float*)d_in[6];
    const float* Wfc  = (const float*)d_in[7];
    const float* bfc  = (const float*)d_in[8];
    float*       out  = (float*)d_out;

    k_detect  <<<1, 32>>>(ei);                            // 0
    k_deg     <<<N_EDGES / 256, 256>>>(ei);               // 1
    k_scan1   <<<128, 256>>>();                           // 2
    k_scan3   <<<N_NODES / 256, 256>>>();                 // 3
    k_fill_xw1<<<8192 + N_NODES / 32, 256>>>(ei, x, W1);  // 4
    k_gather<0><<<N_NODES / 32, 256>>>(b1, batch);        // 5  <- ncu -s 5 target
    k_layer2m <<<N_NODES / 64, 256>>>(W2);                // 6
    k_gather<1><<<N_NODES / 32, 256>>>(b2, batch);        // 7
    k_fc      <<<N_GRAPHS / 256, 256>>>(Wfc, bfc, out);   // 8
}